// round 11
// baseline (speedup 1.0000x reference)
#include <cuda_runtime.h>
#include <math.h>

#define N_PIX_MAX 4194304
#define N_BINS    350000
#define TAPS      901
#define HALF      450
#define CHALF     900                       // composite kernel half-width
#define COMP_N    2112                      // composite kernel storage (>=1801)
#define CONV_THREADS 256
#define RPT       8                         // float2 output-pairs per thread
#define RING      8                         // u64 ring slots (elements mod 8)
#define HTILE     (CONV_THREADS * RPT)      // 2048 (per half)
#define TILE_OUT  (2 * HTILE)               // 4096 outputs per block
#define RAW2      (HTILE + 2*CHALF + 16)    // 3864 float2 window (+refill slack)
#define PAD2      (RAW2 + (RAW2 >> 3))      // bank-conflict padding (1 per 8)
#define WSH2_N    512                       // composite support slots (<=504 taps)
#define P2(i)     ((i) + ((i) >> 3))
#define EW        456                       // edge-exact region per side
#define SMID_N    912                       // mid values needed per side

typedef unsigned long long u64;

// ---------------- device scratch (no allocations allowed) ----------------
__device__ float g_rot[TAPS];
__device__ float g_gauss[TAPS];
__device__ float g_comp[COMP_N];            // composite kernel K = k1 (*) k2
__device__ int   g_lo8;                     // composite support lo, 8-aligned
__device__ int   g_nblk;                    // # of 8-tap blocks
__device__ int   g_b[4];                    // lo0, hi0, lo1, hi1 (exact bounds)
__device__ __align__(16) float g_conv[N_PIX_MAX];   // conv result
__device__ float g_sums[N_BINS];
__device__ float g_cnts[N_BINS];

// ---------------- zero the bin accumulators (graph replays!) -------------
__global__ void zero_kernel() {
    int i = blockIdx.x * blockDim.x + threadIdx.x;
    int stride = gridDim.x * blockDim.x;
    for (int j = i; j < N_BINS; j += stride) {
        g_sums[j] = 0.0f;
        g_cnts[j] = 0.0f;
    }
}

// ------- build k1, k2, composite K = k1*k2, and support bounds -----------
__global__ void setup_kernel(const float* __restrict__ ln_sigma,
                             const float* __restrict__ ln_vsini) {
    __shared__ float red[1024];
    __shared__ float sk1[904], sk2[904];
    __shared__ int s_lo0, s_hi0, s_lo1, s_hi1;
    int tid = threadIdx.x;
    if (tid == 0) { s_lo0 = TAPS; s_hi0 = -1; s_lo1 = TAPS; s_hi1 = -1; }
    __syncthreads();

    float vsini = 0.9f + expf(ln_vsini[0]);
    float sigma = 0.01f + expf(ln_sigma[0]);

    float w  = 0.0f;   // rotational tap (pre-normalization)
    float gw = 0.0f;   // gaussian tap
    if (tid < TAPS) {
        float g = -4.5f + 0.01f * (float)tid;   // linspace(-4.5,4.5,901)
        float x  = (299792.458f * g / 10500.0f) / vsini;
        float x2 = fminf(x * x, 1.0f);
        if (x2 < 0.99999999f) {
            w = 2.0f * sqrtf(1.0f - x2);
            atomicMin(&s_lo0, tid);
            atomicMax(&s_hi0, tid);
        }
        float e = expf(-0.5f * g * g / (sigma * sigma));
        // ~4.5-sigma cutoff: truncated tail mass ~3.4e-6 relative (<< 1e-3 tol)
        if (e >= 4e-5f) {
            atomicMin(&s_lo1, tid);
            atomicMax(&s_hi1, tid);
        }
        gw = (0.01f / (sigma * sqrtf(2.0f * 3.1415926654f))) * e;
    }

    // block sum of rotational kernel for normalization
    red[tid] = w;
    __syncthreads();
    for (int s = 512; s > 0; s >>= 1) {
        if (tid < s) red[tid] += red[tid + s];
        __syncthreads();
    }
    float total = red[0];

    if (tid < TAPS) {
        float k1 = w / total;
        sk1[tid] = k1;  g_rot[tid]   = k1;
        sk2[tid] = gw;  g_gauss[tid] = gw;
    } else if (tid < 904) {
        sk1[tid] = 0.0f;
        sk2[tid] = 0.0f;
    }
    __syncthreads();

    // composite K[c] = sum_a k1[a] * k2[c-a]; support [lo0+lo1, hi0+hi1]
    int lo0 = s_lo0, hi0 = s_hi0, lo1 = s_lo1, hi1 = s_hi1;
    for (int c = tid; c < COMP_N; c += 1024) {
        float s = 0.0f;
        int a0 = max(lo0, c - hi1);
        int a1 = min(hi0, c - lo1);
        for (int a = a0; a <= a1; ++a)
            s += sk1[a] * sk2[c - a];
        g_comp[c] = s;
    }
    if (tid == 0) {
        int lo = lo0 + lo1;
        int hi = hi0 + hi1;
        int lo8 = lo & ~7;
        int nblk = ((hi - lo8 + 1) + 7) >> 3;
        if (nblk > (WSH2_N - 8) / 8) nblk = (WSH2_N - 8) / 8;  // safety clamp
        g_lo8  = lo8;
        g_nblk = nblk;
        g_b[0] = lo0; g_b[1] = hi0; g_b[2] = lo1; g_b[3] = hi1;
    }
}

// -------- fused tiled conv (composite kernel), f32x2 sliding ring --------
// Single pass: out[i] = sum_c K[c] * f[i + c - 900].  Identical inner-loop
// structure to the two-pass version (incremental swizzled indexing, packed
// {w,w} weights, 1-tap prefetch); only the half-width and weight source differ.
__global__ void __launch_bounds__(CONV_THREADS, 5)
conv_kernel(const float* __restrict__ in, int n) {
    __shared__ float2 sh2[PAD2];
    __shared__ float2 wsh2[WSH2_N];

    const int lo8  = g_lo8;            // multiple of 8
    const int nblk = g_nblk;           // number of 8-tap blocks

    const int tile0 = blockIdx.x * TILE_OUT;
    const int tid   = threadIdx.x;

    for (int j = tid; j < WSH2_N; j += CONV_THREADS) {
        int c = lo8 + j;
        float wv = (c < COMP_N) ? g_comp[c] : 0.0f;
        wsh2[j] = make_float2(wv, wv);
    }
    for (int j = tid; j < RAW2; j += CONV_THREADS) {
        int g1 = tile0 - CHALF + j;
        int g2 = g1 + HTILE;
        float a = (g1 >= 0 && g1 < n) ? in[g1] : 0.0f;
        float b = (g2 >= 0 && g2 < n) ? in[g2] : 0.0f;
        sh2[P2(j)] = make_float2(a, b);
    }
    __syncthreads();

    const int base = tid * RPT;        // float2-index of first output pair
    u64 x[RING], acc[RPT];
    int roff = P2(base + lo8);         // padded index of ring start
#pragma unroll
    for (int s = 0; s < RING; ++s) {
        x[s]   = *(const u64*)&sh2[roff + s];     // P2(k0+s)=P2(k0)+s, s<8
        acc[s] = 0ull;                 // (0.0f, 0.0f)
    }
    roff += 9;                         // refill base: P2(k0+8) = P2(k0)+9

    int woff = 0;                      // weight index within wsh2
    u64 wp_cur = *(const u64*)&wsh2[0];          // prefetched packed weight
    for (int b = 0; b < nblk; ++b) {
#pragma unroll
        for (int u = 0; u < 8; ++u) {  // tap c = lo8 + 8*b + u
            u64 wp_nxt = *(const u64*)&wsh2[woff + u + 1];  // prefetch next tap
            // r=0 is the last consumer of slot u -> FMA first, then refill
            asm("fma.rn.f32x2 %0, %1, %2, %0;"
                : "+l"(acc[0]) : "l"(x[u]), "l"(wp_cur));
            u64 xfill = *(const u64*)&sh2[roff + u];        // element tap+8
#pragma unroll
            for (int r = 1; r < RPT; ++r) {
                asm("fma.rn.f32x2 %0, %1, %2, %0;"
                    : "+l"(acc[r]) : "l"(x[(u + r) & 7]), "l"(wp_cur));
            }
            x[u] = xfill;
            wp_cur = wp_nxt;
        }
        roff += 9;                     // next block's refill base
        woff += 8;
    }

    // unpack: low 32 bits = first-half output, high = second-half
    float lo_v[RPT], hi_v[RPT];
#pragma unroll
    for (int r = 0; r < RPT; ++r) {
        lo_v[r] = __int_as_float((int)(acc[r] & 0xFFFFFFFFull));
        hi_v[r] = __int_as_float((int)(acc[r] >> 32));
    }

    int o1 = tile0 + base;
    int o2 = o1 + HTILE;
    if (o1 + RPT <= n) {
        *(float4*)(g_conv + o1)     = make_float4(lo_v[0], lo_v[1], lo_v[2], lo_v[3]);
        *(float4*)(g_conv + o1 + 4) = make_float4(lo_v[4], lo_v[5], lo_v[6], lo_v[7]);
    } else {
#pragma unroll
        for (int r = 0; r < RPT; ++r)
            if (o1 + r < n) g_conv[o1 + r] = lo_v[r];
    }
    if (o2 + RPT <= n) {
        *(float4*)(g_conv + o2)     = make_float4(hi_v[0], hi_v[1], hi_v[2], hi_v[3]);
        *(float4*)(g_conv + o2 + 4) = make_float4(hi_v[4], hi_v[5], hi_v[6], hi_v[7]);
    } else {
#pragma unroll
        for (int r = 0; r < RPT; ++r)
            if (o2 + r < n) g_conv[o2 + r] = hi_v[r];
    }
}

// ------- exact two-stage recompute of the first/last EW outputs ----------
// Two sequential 'same' convs clip the intermediate to [0,n); the composite
// kernel does not. Recompute the edge region exactly (block 0 = low side,
// block 1 = high side).
__global__ void edge_kernel(const float* __restrict__ f, int n) {
    __shared__ float sk1[904], sk2[904], smid[SMID_N];
    int tid = threadIdx.x;
    int side = blockIdx.x;

    for (int j = tid; j < 904; j += blockDim.x) {
        sk1[j] = (j < TAPS) ? g_rot[j]   : 0.0f;
        sk2[j] = (j < TAPS) ? g_gauss[j] : 0.0f;
    }
    __syncthreads();

    int lo0 = g_b[0], hi0 = g_b[1], lo1 = g_b[2], hi1 = g_b[3];

    // stage 1: mid[j] for the SMID_N positions nearest this edge
    for (int m = tid; m < SMID_N; m += blockDim.x) {
        int j = side ? (n - SMID_N + m) : m;
        float s = 0.0f;
        if (j >= 0 && j < n) {
            for (int a = lo0; a <= hi0; ++a) {
                int fi = j + a - HALF;
                if (fi >= 0 && fi < n) s += sk1[a] * f[fi];
            }
        }
        smid[m] = s;
    }
    __syncthreads();

    // stage 2: out[i] for EW outputs at this edge, with mid clipped to [0,n)
    for (int il = tid; il < EW; il += blockDim.x) {
        int i = side ? (n - EW + il) : il;
        if (i < 0 || i >= n) continue;
        float s = 0.0f;
        for (int b = lo1; b <= hi1; ++b) {
            int j = i + b - HALF;
            if (j < 0 || j >= n) continue;          // the 'same'-conv clipping
            int m = side ? (j - (n - SMID_N)) : j;
            if (m < 0 || m >= SMID_N) continue;     // structurally unreachable
            s += sk2[b] * smid[m];
        }
        g_conv[i] = s;
    }
}

// ---------------- sorted segment sum/count (run-length + atomics) --------
__global__ void seg_kernel(const int* __restrict__ ids, int n) {
    long long tidg = (long long)(blockIdx.x * blockDim.x + threadIdx.x);
    int base = (int)(tidg * 8);
    if (base >= n) return;
    int end = base + 8;
    if (end > n) end = n;

    int   cur = ids[base];
    float s = 0.0f, c = 0.0f;
    for (int k = base; k < end; ++k) {
        int id = ids[k];
        if (id != cur) {
            atomicAdd(&g_sums[cur], s);
            atomicAdd(&g_cnts[cur], c);
            cur = id; s = 0.0f; c = 0.0f;
        }
        s += g_conv[k];
        c += 1.0f;
    }
    atomicAdd(&g_sums[cur], s);
    atomicAdd(&g_cnts[cur], c);
}

// ---------------- means, clip, drop first/last bin -----------------------
__global__ void final_kernel(float* __restrict__ out, int n_out) {
    int i = blockIdx.x * blockDim.x + threadIdx.x;
    if (i < n_out) {
        int id = i + 1;
        float c = g_cnts[id];
        float m = g_sums[id] / fmaxf(c, 1.0f);
        out[i] = fminf(fmaxf(m, 0.0f), 1.0f);
    }
}

extern "C" void kernel_launch(void* const* d_in, const int* in_sizes, int n_in,
                              void* d_out, int out_size) {
    const float* flux     = (const float*)d_in[0];
    const float* ln_sigma = (const float*)d_in[1];
    const float* ln_vsini = (const float*)d_in[2];
    const int*   ids      = (const int*)d_in[3];
    int n = in_sizes[0];

    zero_kernel<<<684, 512>>>();
    setup_kernel<<<1, 1024>>>(ln_sigma, ln_vsini);

    int conv_blocks = (n + TILE_OUT - 1) / TILE_OUT;
    conv_kernel<<<conv_blocks, CONV_THREADS>>>(flux, n);
    edge_kernel<<<2, 512>>>(flux, n);

    int seg_threads = (n + 7) / 8;
    seg_kernel<<<(seg_threads + 255) / 256, 256>>>(ids, n);

    final_kernel<<<(out_size + 255) / 256, 256>>>((float*)d_out, out_size);
}

// round 12
// speedup vs baseline: 1.0586x; 1.0586x over previous
#include <cuda_runtime.h>
#include <math.h>

#define N_PIX_MAX 4194304
#define N_BINS    350000
#define TAPS      901
#define HALF      450
#define CHALF     900                       // composite kernel half-width
#define COMP_N    2112                      // composite kernel storage (>=1801)
#define CONV_THREADS 256
#define RPT       8                         // float2 output-pairs per thread
#define RING      8                         // u64 ring slots (elements mod 8)
#define HTILE     (CONV_THREADS * RPT)      // 2048 (per half)
#define TILE_OUT  (2 * HTILE)               // 4096 outputs per block
#define RAW2      (HTILE + 2*CHALF + 16)    // 3864 float2 window (+refill slack)
#define PAD2      (RAW2 + (RAW2 >> 3))      // bank-conflict padding (1 per 8)
#define WSH2_N    512                       // composite support slots (<=504 taps)
#define P2(i)     ((i) + ((i) >> 3))
#define EW        456                       // edge-exact region per side
#define SMID_N    912                       // mid values needed per side
#define EDGE_F    1376                      // smem f region per side (>=1362)

typedef unsigned long long u64;

// ---------------- device scratch (no allocations allowed) ----------------
__device__ float g_rot[TAPS];
__device__ float g_gauss[TAPS];
__device__ float g_comp[COMP_N];            // composite kernel K = k1 (*) k2
__device__ int   g_lo8;                     // composite support lo, 8-aligned
__device__ int   g_nblk;                    // # of 8-tap blocks
__device__ int   g_b[4];                    // lo0, hi0, lo1, hi1 (exact bounds)
__device__ __align__(16) float g_conv[N_PIX_MAX];   // conv result
__device__ float g_sums[N_BINS];
__device__ float g_cnts[N_BINS];

// ---------------- zero the bin accumulators (graph replays!) -------------
__global__ void zero_kernel() {
    int i = blockIdx.x * blockDim.x + threadIdx.x;
    int stride = gridDim.x * blockDim.x;
    for (int j = i; j < N_BINS; j += stride) {
        g_sums[j] = 0.0f;
        g_cnts[j] = 0.0f;
    }
}

// ------- build k1, k2, composite K = k1*k2, and support bounds -----------
__global__ void setup_kernel(const float* __restrict__ ln_sigma,
                             const float* __restrict__ ln_vsini) {
    __shared__ float red[1024];
    __shared__ float sk1[904], sk2[904];
    __shared__ int s_lo0, s_hi0, s_lo1, s_hi1;
    int tid = threadIdx.x;
    if (tid == 0) { s_lo0 = TAPS; s_hi0 = -1; s_lo1 = TAPS; s_hi1 = -1; }
    __syncthreads();

    float vsini = 0.9f + expf(ln_vsini[0]);
    float sigma = 0.01f + expf(ln_sigma[0]);

    float w  = 0.0f;   // rotational tap (pre-normalization)
    float gw = 0.0f;   // gaussian tap
    if (tid < TAPS) {
        float g = -4.5f + 0.01f * (float)tid;   // linspace(-4.5,4.5,901)
        float x  = (299792.458f * g / 10500.0f) / vsini;
        float x2 = fminf(x * x, 1.0f);
        if (x2 < 0.99999999f) {
            w = 2.0f * sqrtf(1.0f - x2);
            atomicMin(&s_lo0, tid);
            atomicMax(&s_hi0, tid);
        }
        float e = expf(-0.5f * g * g / (sigma * sigma));
        // ~4.5-sigma cutoff: truncated tail mass ~3.4e-6 relative (<< 1e-3 tol)
        if (e >= 4e-5f) {
            atomicMin(&s_lo1, tid);
            atomicMax(&s_hi1, tid);
        }
        gw = (0.01f / (sigma * sqrtf(2.0f * 3.1415926654f))) * e;
    }

    // block sum of rotational kernel for normalization
    red[tid] = w;
    __syncthreads();
    for (int s = 512; s > 0; s >>= 1) {
        if (tid < s) red[tid] += red[tid + s];
        __syncthreads();
    }
    float total = red[0];

    if (tid < TAPS) {
        float k1 = w / total;
        sk1[tid] = k1;  g_rot[tid]   = k1;
        sk2[tid] = gw;  g_gauss[tid] = gw;
    } else if (tid < 904) {
        sk1[tid] = 0.0f;
        sk2[tid] = 0.0f;
    }
    __syncthreads();

    // composite K[c] = sum_a k1[a] * k2[c-a]; support [lo0+lo1, hi0+hi1]
    int lo0 = s_lo0, hi0 = s_hi0, lo1 = s_lo1, hi1 = s_hi1;
    for (int c = tid; c < COMP_N; c += 1024) {
        float s = 0.0f;
        int a0 = max(lo0, c - hi1);
        int a1 = min(hi0, c - lo1);
        for (int a = a0; a <= a1; ++a)
            s += sk1[a] * sk2[c - a];
        g_comp[c] = s;
    }
    if (tid == 0) {
        int lo = lo0 + lo1;
        int hi = hi0 + hi1;
        int lo8 = lo & ~7;
        int nblk = ((hi - lo8 + 1) + 7) >> 3;
        if (nblk > (WSH2_N - 8) / 8) nblk = (WSH2_N - 8) / 8;  // safety clamp
        g_lo8  = lo8;
        g_nblk = nblk;
        g_b[0] = lo0; g_b[1] = hi0; g_b[2] = lo1; g_b[3] = hi1;
    }
}

// -------- fused tiled conv (composite kernel), f32x2 sliding ring --------
// Single pass: out[i] = sum_c K[c] * f[i + c - 900].  Incremental swizzled
// indexing, packed {w,w} weights, 1-tap weight prefetch.
__global__ void __launch_bounds__(CONV_THREADS, 5)
conv_kernel(const float* __restrict__ in, int n) {
    __shared__ float2 sh2[PAD2];
    __shared__ float2 wsh2[WSH2_N];

    const int lo8  = g_lo8;            // multiple of 8
    const int nblk = g_nblk;           // number of 8-tap blocks

    const int tile0 = blockIdx.x * TILE_OUT;
    const int tid   = threadIdx.x;

    for (int j = tid; j < WSH2_N; j += CONV_THREADS) {
        int c = lo8 + j;
        float wv = (c < COMP_N) ? g_comp[c] : 0.0f;
        wsh2[j] = make_float2(wv, wv);
    }
    for (int j = tid; j < RAW2; j += CONV_THREADS) {
        int g1 = tile0 - CHALF + j;
        int g2 = g1 + HTILE;
        float a = (g1 >= 0 && g1 < n) ? in[g1] : 0.0f;
        float b = (g2 >= 0 && g2 < n) ? in[g2] : 0.0f;
        sh2[P2(j)] = make_float2(a, b);
    }
    __syncthreads();

    const int base = tid * RPT;        // float2-index of first output pair
    u64 x[RING], acc[RPT];
    int roff = P2(base + lo8);         // padded index of ring start
#pragma unroll
    for (int s = 0; s < RING; ++s) {
        x[s]   = *(const u64*)&sh2[roff + s];     // P2(k0+s)=P2(k0)+s, s<8
        acc[s] = 0ull;                 // (0.0f, 0.0f)
    }
    roff += 9;                         // refill base: P2(k0+8) = P2(k0)+9

    int woff = 0;                      // weight index within wsh2
    u64 wp_cur = *(const u64*)&wsh2[0];          // prefetched packed weight
    for (int b = 0; b < nblk; ++b) {
#pragma unroll
        for (int u = 0; u < 8; ++u) {  // tap c = lo8 + 8*b + u
            u64 wp_nxt = *(const u64*)&wsh2[woff + u + 1];  // prefetch next tap
            // r=0 is the last consumer of slot u -> FMA first, then refill
            asm("fma.rn.f32x2 %0, %1, %2, %0;"
                : "+l"(acc[0]) : "l"(x[u]), "l"(wp_cur));
            u64 xfill = *(const u64*)&sh2[roff + u];        // element tap+8
#pragma unroll
            for (int r = 1; r < RPT; ++r) {
                asm("fma.rn.f32x2 %0, %1, %2, %0;"
                    : "+l"(acc[r]) : "l"(x[(u + r) & 7]), "l"(wp_cur));
            }
            x[u] = xfill;
            wp_cur = wp_nxt;
        }
        roff += 9;                     // next block's refill base
        woff += 8;
    }

    // unpack: low 32 bits = first-half output, high = second-half
    float lo_v[RPT], hi_v[RPT];
#pragma unroll
    for (int r = 0; r < RPT; ++r) {
        lo_v[r] = __int_as_float((int)(acc[r] & 0xFFFFFFFFull));
        hi_v[r] = __int_as_float((int)(acc[r] >> 32));
    }

    int o1 = tile0 + base;
    int o2 = o1 + HTILE;
    if (o1 + RPT <= n) {
        *(float4*)(g_conv + o1)     = make_float4(lo_v[0], lo_v[1], lo_v[2], lo_v[3]);
        *(float4*)(g_conv + o1 + 4) = make_float4(lo_v[4], lo_v[5], lo_v[6], lo_v[7]);
    } else {
#pragma unroll
        for (int r = 0; r < RPT; ++r)
            if (o1 + r < n) g_conv[o1 + r] = lo_v[r];
    }
    if (o2 + RPT <= n) {
        *(float4*)(g_conv + o2)     = make_float4(hi_v[0], hi_v[1], hi_v[2], hi_v[3]);
        *(float4*)(g_conv + o2 + 4) = make_float4(hi_v[4], hi_v[5], hi_v[6], hi_v[7]);
    } else {
#pragma unroll
        for (int r = 0; r < RPT; ++r)
            if (o2 + r < n) g_conv[o2 + r] = hi_v[r];
    }
}

// ------- exact two-stage recompute of the first/last EW outputs ----------
// SMEM-resident: the edge f region (<=1362 floats per side) is staged into
// shared once; both stages then run from smem. Block 0 = low side, 1 = high.
__global__ void edge_kernel(const float* __restrict__ f, int n) {
    __shared__ float sk1[904], sk2[904], smid[SMID_N], sf[EDGE_F];
    int tid = threadIdx.x;
    int side = blockIdx.x;

    for (int j = tid; j < 904; j += blockDim.x) {
        sk1[j] = (j < TAPS) ? g_rot[j]   : 0.0f;
        sk2[j] = (j < TAPS) ? g_gauss[j] : 0.0f;
    }
    // stage 0: coalesced load of the edge f region into smem
    int f0 = side ? (n - EDGE_F) : 0;  // global index of sf[0]
    for (int j = tid; j < EDGE_F; j += blockDim.x) {
        int gi = f0 + j;
        sf[j] = (gi >= 0 && gi < n) ? f[gi] : 0.0f;
    }
    __syncthreads();

    int lo0 = g_b[0], hi0 = g_b[1], lo1 = g_b[2], hi1 = g_b[3];

    // stage 1: mid[j] for the SMID_N positions nearest this edge (from smem)
    for (int m = tid; m < SMID_N; m += blockDim.x) {
        int j = side ? (n - SMID_N + m) : m;
        float s = 0.0f;
        for (int a = lo0; a <= hi0; ++a) {
            int fi = j + a - HALF;
            if (fi >= 0 && fi < n) s += sk1[a] * sf[fi - f0];
        }
        smid[m] = s;
    }
    __syncthreads();

    // stage 2: out[i] for EW outputs at this edge, with mid clipped to [0,n)
    for (int il = tid; il < EW; il += blockDim.x) {
        int i = side ? (n - EW + il) : il;
        if (i < 0 || i >= n) continue;
        float s = 0.0f;
        for (int b = lo1; b <= hi1; ++b) {
            int j = i + b - HALF;
            if (j < 0 || j >= n) continue;          // the 'same'-conv clipping
            int m = side ? (j - (n - SMID_N)) : j;
            if (m < 0 || m >= SMID_N) continue;     // structurally unreachable
            s += sk2[b] * smid[m];
        }
        g_conv[i] = s;
    }
}

// ---------------- sorted segment sum/count (run-length + atomics) --------
__global__ void seg_kernel(const int* __restrict__ ids, int n) {
    long long tidg = (long long)(blockIdx.x * blockDim.x + threadIdx.x);
    int base = (int)(tidg * 8);
    if (base >= n) return;
    int end = base + 8;
    if (end > n) end = n;

    int   cur = ids[base];
    float s = 0.0f, c = 0.0f;
    for (int k = base; k < end; ++k) {
        int id = ids[k];
        if (id != cur) {
            atomicAdd(&g_sums[cur], s);
            atomicAdd(&g_cnts[cur], c);
            cur = id; s = 0.0f; c = 0.0f;
        }
        s += g_conv[k];
        c += 1.0f;
    }
    atomicAdd(&g_sums[cur], s);
    atomicAdd(&g_cnts[cur], c);
}

// ---------------- means, clip, drop first/last bin -----------------------
__global__ void final_kernel(float* __restrict__ out, int n_out) {
    int i = blockIdx.x * blockDim.x + threadIdx.x;
    if (i < n_out) {
        int id = i + 1;
        float c = g_cnts[id];
        float m = g_sums[id] / fmaxf(c, 1.0f);
        out[i] = fminf(fmaxf(m, 0.0f), 1.0f);
    }
}

extern "C" void kernel_launch(void* const* d_in, const int* in_sizes, int n_in,
                              void* d_out, int out_size) {
    const float* flux     = (const float*)d_in[0];
    const float* ln_sigma = (const float*)d_in[1];
    const float* ln_vsini = (const float*)d_in[2];
    const int*   ids      = (const int*)d_in[3];
    int n = in_sizes[0];

    zero_kernel<<<684, 512>>>();
    setup_kernel<<<1, 1024>>>(ln_sigma, ln_vsini);

    int conv_blocks = (n + TILE_OUT - 1) / TILE_OUT;
    conv_kernel<<<conv_blocks, CONV_THREADS>>>(flux, n);
    edge_kernel<<<2, 1024>>>(flux, n);

    int seg_threads = (n + 7) / 8;
    seg_kernel<<<(seg_threads + 255) / 256, 256>>>(ids, n);

    final_kernel<<<(out_size + 255) / 256, 256>>>((float*)d_out, out_size);
}